// round 11
// baseline (speedup 1.0000x reference)
#include <cuda_runtime.h>

// LIF scan: T=16, N = 4,194,304 sites. HBM-bound streaming (256 MiB in, 256 MiB out).
// Rounds 1-9: every scheduling knob (occupancy 31-85%, MLP 2-16, R/W phasing,
// waves, row locality, store policy, block size) pins at ~6.3 TB/s (80% spec).
// R10 failed with "device busy" at harness device-acquire (infra, not kernel).
// R11: clean retry of the untested axis — ACCESS WIDTH. sm_103a supports
// 256-bit global ld/st (ld/st.global.v8.f32 -> LDG.E.256/STG.E.256). Halves
// request count; each warp instruction covers 8KB contiguous (2 full 128B
// lines). One thread per 8 consecutive floats (32B-aligned), block 256.

#ifndef LIF_T
#define LIF_T 16
#endif

__device__ __forceinline__ void ldg256(const float* __restrict__ p, float* r) {
    asm volatile(
        "ld.global.nc.v8.f32 {%0,%1,%2,%3,%4,%5,%6,%7}, [%8];"
        : "=f"(r[0]), "=f"(r[1]), "=f"(r[2]), "=f"(r[3]),
          "=f"(r[4]), "=f"(r[5]), "=f"(r[6]), "=f"(r[7])
        : "l"(p));
}

__device__ __forceinline__ void stg256(float* __restrict__ p, const float* r) {
    asm volatile(
        "st.global.v8.f32 [%0], {%1,%2,%3,%4,%5,%6,%7,%8};"
        :: "l"(p),
           "f"(r[0]), "f"(r[1]), "f"(r[2]), "f"(r[3]),
           "f"(r[4]), "f"(r[5]), "f"(r[6]), "f"(r[7])
        : "memory");
}

__global__ void __launch_bounds__(256) lif_kernel(
    const float* __restrict__ in,    // [T, N]
    float* __restrict__ out,         // [T, N]
    int n)                           // N = 4,194,304
{
    const int i = blockIdx.x * blockDim.x + threadIdx.x;  // v8 lane index
    const int n8 = n >> 3;
    if (i >= n8) return;

    const float decay = 0.5f;
    const float thr   = 1.0f;

    const float* __restrict__ ip = in  + (size_t)i * 8;
    float* __restrict__       op = out + (size_t)i * 8;

    float v[8];
    #pragma unroll
    for (int k = 0; k < 8; ++k) v[k] = 0.0f;

    #pragma unroll
    for (int t = 0; t < LIF_T; ++t) {
        float x[8];
        ldg256(ip + (size_t)t * n, x);

        float s[8];
        #pragma unroll
        for (int k = 0; k < 8; ++k) {
            v[k] = fmaf(v[k], decay, x[k]);
            s[k] = (v[k] >= thr) ? 1.0f : 0.0f;
            v[k] -= s[k] * thr;
        }

        stg256(op + (size_t)t * n, s);
    }
}

extern "C" void kernel_launch(void* const* d_in, const int* in_sizes, int n_in,
                              void* d_out, int out_size)
{
    const float* in = (const float*)d_in[0];
    float* out = (float*)d_out;

    const int total = in_sizes[0];            // T * N = 67,108,864
    const int n = total / LIF_T;              // N = 4,194,304 (sites)
    const int n8 = n / 8;                     // 524,288 v8 lanes

    const int block = 256;
    const int grid = (n8 + block - 1) / block;   // 2048

    lif_kernel<<<grid, block>>>(in, out, n);
}

// round 12
// speedup vs baseline: 1.0229x; 1.0229x over previous
#include <cuda_runtime.h>

// LIF scan: T=16, N = 4,194,304 sites. HBM-bound streaming (256 MiB in, 256 MiB out).
// FINAL — roofline-pinned. Eleven rounds of evidence: occupancy (31-85%),
// per-thread MLP (2-16), warp R/W phasing, wave structure (1 vs 3.5),
// per-CTA row footprint (4-16 KiB), store cache policy (.cs vs default),
// block size (256/512/1024), and access width (128-bit vs 256-bit LDG/STG)
// are ALL non-binding — every variant pins at 6.27-6.36 TB/s (~80% of the
// 8 TB/s spec). Traffic is provably minimal (serial recurrence: exactly one
// read + one write per element, zero exploitable reuse); compute/issue <11%.
// The residual ~20% is HBM-controller-level (refresh + 50/50 R/W bus
// turnaround) and is not addressable from the SM.
//
// Config (best measured, reproduced: ncu 76.0us, bench 82.4us): one thread
// per 4 sites (float4), time loop in 2 groups of 8: 8 front-batched LDG.128
// -> serial v-chain in registers -> 8 batched STG.128, .cs hints both ways.

#ifndef LIF_T
#define LIF_T 16
#endif
#define TBATCH 8

__global__ void __launch_bounds__(256) lif_kernel(
    const float4* __restrict__ in,   // [T, N/4] float4
    float4* __restrict__ out,        // [T, N/4] float4
    int n4)                          // N/4
{
    const int i = blockIdx.x * blockDim.x + threadIdx.x;
    if (i >= n4) return;

    const float decay = 0.5f;
    const float thr   = 1.0f;

    float vx = 0.0f, vy = 0.0f, vz = 0.0f, vw = 0.0f;

    const float4* __restrict__ ip = in + i;
    float4* __restrict__ op = out + i;

    #pragma unroll
    for (int tb = 0; tb < LIF_T; tb += TBATCH) {
        // Phase 1: 8 front-batched streaming loads (independent LDG.128)
        float4 x[TBATCH];
        #pragma unroll
        for (int j = 0; j < TBATCH; ++j) {
            x[j] = __ldcs(ip + (size_t)(tb + j) * n4);
        }

        // Phase 2: serial LIF chain entirely in registers
        #pragma unroll
        for (int j = 0; j < TBATCH; ++j) {
            vx = fmaf(vx, decay, x[j].x);
            vy = fmaf(vy, decay, x[j].y);
            vz = fmaf(vz, decay, x[j].z);
            vw = fmaf(vw, decay, x[j].w);

            const float sx = (vx >= thr) ? 1.0f : 0.0f;
            const float sy = (vy >= thr) ? 1.0f : 0.0f;
            const float sz = (vz >= thr) ? 1.0f : 0.0f;
            const float sw = (vw >= thr) ? 1.0f : 0.0f;

            vx -= sx * thr;
            vy -= sy * thr;
            vz -= sz * thr;
            vw -= sw * thr;

            x[j].x = sx; x[j].y = sy; x[j].z = sz; x[j].w = sw;
        }

        // Phase 3: 8 batched streaming stores (STG.128)
        #pragma unroll
        for (int j = 0; j < TBATCH; ++j) {
            __stcs(op + (size_t)(tb + j) * n4, x[j]);
        }
    }
}

extern "C" void kernel_launch(void* const* d_in, const int* in_sizes, int n_in,
                              void* d_out, int out_size)
{
    const float* in = (const float*)d_in[0];
    float* out = (float*)d_out;

    const int total = in_sizes[0];            // T * N = 67,108,864
    const int n = total / LIF_T;              // N = 4,194,304 (sites)
    const int n4 = n / 4;                     // 1,048,576 float4 lanes

    const int block = 256;
    const int grid = (n4 + block - 1) / block;   // 4096

    lif_kernel<<<grid, block>>>((const float4*)in, (float4*)out, n4);
}